// round 3
// baseline (speedup 1.0000x reference)
#include <cuda_runtime.h>
#include <cuda_bf16.h>

// NCEAverage: out[b,k] = exp(dot(memory[idx'[b,k]], x[b]) / T) / Z
// idx'[b,0] = y[b];  Z = mean(out_unnorm) * N
// B=256, K=4096, D=128, N=1e6, T=0.07

#define B_SZ 256
#define K_SZ 4096
#define D_SZ 128
#define N_SZ 1000000
#define INV_T (1.0f / 0.07f)

#define SPLIT 8                       // gridDim.y
#define WARPS 8                       // warps per block
#define KCHUNK (K_SZ / SPLIT)         // 512 k's per block
#define ITERS (KCHUNK / WARPS)        // 64 k's per warp
#define NBLOCKS (B_SZ * SPLIT)        // 2048 blocks / partials

__device__ float g_partials[NBLOCKS];
__device__ float g_scale;
__device__ unsigned int g_ticket;     // zero-init; last block resets to 0

__global__ __launch_bounds__(WARPS * 32, 6)
void nce_scores_kernel(const float* __restrict__ x,
                       const int* __restrict__ y,
                       const int* __restrict__ idx,
                       const float* __restrict__ memory,
                       float* __restrict__ out) {
    const int b    = blockIdx.x;
    const int lane = threadIdx.x & 31;
    const int warp = threadIdx.x >> 5;
    const int k0   = blockIdx.y * KCHUNK;

    // x row for this b: lane l holds elements [4l, 4l+4)
    const float4 xv = reinterpret_cast<const float4*>(x + b * D_SZ)[lane];

    const int* idx_b = idx + (size_t)b * K_SZ;
    float wsum = 0.0f;

    // Each warp: k = k0 + warp + i*WARPS. Unroll x4 for MLP; interleave the
    // four shfl-reduction chains so they pipeline.
    #pragma unroll 1
    for (int i = 0; i < ITERS; i += 4) {
        const int ka = k0 + warp + (i    ) * WARPS;
        const int kb = k0 + warp + (i + 1) * WARPS;
        const int kc = k0 + warp + (i + 2) * WARPS;
        const int kd = k0 + warp + (i + 3) * WARPS;

        const int ra = (ka == 0) ? y[b] : idx_b[ka];   // slot 0 forced positive
        const int rb = idx_b[kb];
        const int rc = idx_b[kc];
        const int rd = idx_b[kd];

        const float4 wa = reinterpret_cast<const float4*>(memory + (size_t)ra * D_SZ)[lane];
        const float4 wb = reinterpret_cast<const float4*>(memory + (size_t)rb * D_SZ)[lane];
        const float4 wc = reinterpret_cast<const float4*>(memory + (size_t)rc * D_SZ)[lane];
        const float4 wd = reinterpret_cast<const float4*>(memory + (size_t)rd * D_SZ)[lane];

        float da = wa.x * xv.x + wa.y * xv.y + wa.z * xv.z + wa.w * xv.w;
        float db = wb.x * xv.x + wb.y * xv.y + wb.z * xv.z + wb.w * xv.w;
        float dc = wc.x * xv.x + wc.y * xv.y + wc.z * xv.z + wc.w * xv.w;
        float dd = wd.x * xv.x + wd.y * xv.y + wd.z * xv.z + wd.w * xv.w;

        #pragma unroll
        for (int s = 16; s > 0; s >>= 1) {
            da += __shfl_xor_sync(0xffffffffu, da, s);
            db += __shfl_xor_sync(0xffffffffu, db, s);
            dc += __shfl_xor_sync(0xffffffffu, dc, s);
            dd += __shfl_xor_sync(0xffffffffu, dd, s);
        }

        if (lane == 0) {
            const float sa = __expf(da * INV_T);
            const float sb = __expf(db * INV_T);
            const float sc = __expf(dc * INV_T);
            const float sd = __expf(dd * INV_T);
            float* ob = out + (size_t)b * K_SZ;
            ob[ka] = sa; ob[kb] = sb; ob[kc] = sc; ob[kd] = sd;
            wsum += (sa + sb) + (sc + sd);
        }
    }

    // Deterministic block partial: lane0 of each warp -> smem, t0 sums in order.
    __shared__ float ssum[WARPS];
    __shared__ bool  s_last;
    if (lane == 0) ssum[warp] = wsum;
    __syncthreads();
    if (threadIdx.x == 0) {
        float t = 0.0f;
        #pragma unroll
        for (int w = 0; w < WARPS; w++) t += ssum[w];
        g_partials[blockIdx.y * gridDim.x + blockIdx.x] = t;
        __threadfence();
        const unsigned int tk = atomicAdd(&g_ticket, 1u);
        s_last = (tk == NBLOCKS - 1);
    }
    __syncthreads();

    // Last-arriving block: reduce all partials (double, fixed order ->
    // deterministic), publish scale, reset ticket for graph replay.
    if (s_last) {
        __shared__ double dsh[WARPS * 32];
        const int t = threadIdx.x;
        double acc = 0.0;
        #pragma unroll
        for (int j = 0; j < NBLOCKS / (WARPS * 32); j++)
            acc += (double)g_partials[t + j * (WARPS * 32)];
        dsh[t] = acc;
        __syncthreads();
        for (int s = (WARPS * 32) / 2; s > 0; s >>= 1) {
            if (t < s) dsh[t] += dsh[t + s];
            __syncthreads();
        }
        if (t == 0) {
            // Z = (sum / (B*K)) * N ; scale = 1/Z  — double avoids fp32
            // overflow (sum ~ 1e31; sum*N would be inf in fp32).
            const double sum = dsh[0];
            g_scale = (float)(((double)B_SZ * (double)K_SZ) /
                              (sum * (double)N_SZ));
            g_ticket = 0u;
            __threadfence();
        }
    }
}

__global__ __launch_bounds__(256)
void nce_norm_kernel(float* __restrict__ out) {
    const float s = g_scale;
    const int i = blockIdx.x * blockDim.x + threadIdx.x;  // over float4s
    float4* o = reinterpret_cast<float4*>(out);
    float4 v = o[i];
    v.x *= s; v.y *= s; v.z *= s; v.w *= s;
    o[i] = v;
}

extern "C" void kernel_launch(void* const* d_in, const int* in_sizes, int n_in,
                              void* d_out, int out_size) {
    const float* x      = (const float*)d_in[0];
    const int*   y      = (const int*)d_in[1];
    const int*   idx    = (const int*)d_in[2];
    const float* memory = (const float*)d_in[3];
    float* out = (float*)d_out;

    dim3 grid1(B_SZ, SPLIT);
    nce_scores_kernel<<<grid1, WARPS * 32>>>(x, y, idx, memory, out);
    const int nvec4 = (B_SZ * K_SZ) / 4;   // 262144
    nce_norm_kernel<<<nvec4 / 256, 256>>>(out);
}

// round 4
// speedup vs baseline: 1.0519x; 1.0519x over previous
#include <cuda_runtime.h>
#include <cuda_bf16.h>

// NCEAverage: out[b,k] = exp(dot(memory[idx'[b,k]], x[b]) / T) / Z
// idx'[b,0] = y[b];  Z = mean(out_unnorm) * N
// B=256, K=4096, D=128, N=1e6, T=0.07

#define B_SZ 256
#define K_SZ 4096
#define D_SZ 128
#define N_SZ 1000000
#define INV_T (1.0f / 0.07f)

#define SPLIT 8                       // gridDim.y
#define WARPS 8                       // warps per block
#define KCHUNK (K_SZ / SPLIT)         // 512 k's per block
#define ITERS (KCHUNK / WARPS)        // 64 k's per warp
#define NBLOCKS (B_SZ * SPLIT)        // 2048 blocks / partials

__device__ float g_partials[NBLOCKS];
__device__ float g_scale;
__device__ unsigned int g_ticket;     // zero-init; last block resets to 0

__global__ __launch_bounds__(WARPS * 32, 8)
void nce_scores_kernel(const float* __restrict__ x,
                       const int* __restrict__ y,
                       const int* __restrict__ idx,
                       const float* __restrict__ memory,
                       float* __restrict__ out) {
    const int b    = blockIdx.x;
    const int lane = threadIdx.x & 31;
    const int warp = threadIdx.x >> 5;
    const int k0   = blockIdx.y * KCHUNK;

    // x row for this b: lane l holds elements [4l, 4l+4)
    const float4 xv = reinterpret_cast<const float4*>(x + b * D_SZ)[lane];

    const int* idx_b = idx + (size_t)b * K_SZ;
    float wsum = 0.0f;

    // Each warp: k = k0 + warp + i*WARPS. Unroll x2 (proven sweet spot:
    // 32 regs, no spills, DRAM ~73%).
    #pragma unroll 1
    for (int i = 0; i < ITERS; i += 2) {
        const int k1 = k0 + warp + (i    ) * WARPS;
        const int k2 = k0 + warp + (i + 1) * WARPS;

        const int row1 = (k1 == 0) ? y[b] : idx_b[k1];
        const int row2 = idx_b[k2];   // k2 >= 8, never the forced-positive slot

        const float4 w1 = reinterpret_cast<const float4*>(memory + (size_t)row1 * D_SZ)[lane];
        const float4 w2 = reinterpret_cast<const float4*>(memory + (size_t)row2 * D_SZ)[lane];

        float d1 = w1.x * xv.x + w1.y * xv.y + w1.z * xv.z + w1.w * xv.w;
        float d2 = w2.x * xv.x + w2.y * xv.y + w2.z * xv.z + w2.w * xv.w;

        #pragma unroll
        for (int s = 16; s > 0; s >>= 1) {
            d1 += __shfl_xor_sync(0xffffffffu, d1, s);
            d2 += __shfl_xor_sync(0xffffffffu, d2, s);
        }

        if (lane == 0) {
            const float s1 = __expf(d1 * INV_T);
            const float s2 = __expf(d2 * INV_T);
            out[(size_t)b * K_SZ + k1] = s1;
            out[(size_t)b * K_SZ + k2] = s2;
            wsum += s1 + s2;
        }
    }

    // Deterministic block partial: lane0 of each warp -> smem, t0 sums in order.
    __shared__ float ssum[WARPS];
    __shared__ bool  s_last;
    if (lane == 0) ssum[warp] = wsum;
    __syncthreads();
    if (threadIdx.x == 0) {
        float t = 0.0f;
        #pragma unroll
        for (int w = 0; w < WARPS; w++) t += ssum[w];
        g_partials[blockIdx.y * gridDim.x + blockIdx.x] = t;
        __threadfence();
        const unsigned int tk = atomicAdd(&g_ticket, 1u);
        s_last = (tk == NBLOCKS - 1);
    }
    __syncthreads();

    // Last-arriving block: reduce all partials (double, fixed order ->
    // deterministic), publish scale, reset ticket for graph replay.
    if (s_last) {
        __shared__ double dsh[WARPS * 32];
        const int t = threadIdx.x;
        double acc = 0.0;
        #pragma unroll
        for (int j = 0; j < NBLOCKS / (WARPS * 32); j++)
            acc += (double)g_partials[t + j * (WARPS * 32)];
        dsh[t] = acc;
        __syncthreads();
        for (int s = (WARPS * 32) / 2; s > 0; s >>= 1) {
            if (t < s) dsh[t] += dsh[t + s];
            __syncthreads();
        }
        if (t == 0) {
            // Z = (sum / (B*K)) * N ; scale = 1/Z  — double avoids fp32
            // overflow (sum ~ 1e31; sum*N would be inf in fp32).
            const double sum = dsh[0];
            g_scale = (float)(((double)B_SZ * (double)K_SZ) /
                              (sum * (double)N_SZ));
            g_ticket = 0u;
            __threadfence();
        }
    }
}

// out has B*K = 1,048,576 floats = 262,144 float4s.
// 256 blocks x 256 threads x 4 float4s each, block-strided.
#define NORM_BLOCKS 256
#define NORM_THREADS 256
#define NORM_V4 ((B_SZ * K_SZ) / 4)

__global__ __launch_bounds__(NORM_THREADS)
void nce_norm_kernel(float* __restrict__ out) {
    const float s = g_scale;
    float4* o = reinterpret_cast<float4*>(out);
    int i = blockIdx.x * NORM_THREADS + threadIdx.x;
    #pragma unroll
    for (int j = 0; j < NORM_V4 / (NORM_BLOCKS * NORM_THREADS); j++) {
        float4 v = o[i];
        v.x *= s; v.y *= s; v.z *= s; v.w *= s;
        o[i] = v;
        i += NORM_BLOCKS * NORM_THREADS;
    }
}

extern "C" void kernel_launch(void* const* d_in, const int* in_sizes, int n_in,
                              void* d_out, int out_size) {
    const float* x      = (const float*)d_in[0];
    const int*   y      = (const int*)d_in[1];
    const int*   idx    = (const int*)d_in[2];
    const float* memory = (const float*)d_in[3];
    float* out = (float*)d_out;

    dim3 grid1(B_SZ, SPLIT);
    nce_scores_kernel<<<grid1, WARPS * 32>>>(x, y, idx, memory, out);
    nce_norm_kernel<<<NORM_BLOCKS, NORM_THREADS>>>(out);
}